// round 14
// baseline (speedup 1.0000x reference)
#include <cuda_runtime.h>

#define DD 64
#define MAXN 100000
#define MAXE 1000000
typedef unsigned long long u64;
typedef unsigned int u32;

__device__ float g_xa[(size_t)MAXN * DD];
__device__ float g_xb[(size_t)MAXN * DD];
__device__ float g_h1[(size_t)MAXE * DD];
__device__ float g_h2[(size_t)MAXN * DD];
__device__ float g_sums[(size_t)MAXN * DD];
__device__ float g_cnt[MAXN];
__device__ float g_st1[128], g_st2[128], g_ss1[128], g_ss2[128];

// dynamic smem (bytes): bf16 planes, padded gather buffer, idx, stats scratch
#define SM_AHI  0
#define SM_ALO  16384
#define SM_GAT  32768              // 128 rows x 68 floats = 34816 B
#define SM_IDX  67584              // 128 ints
#define SM_SST  68096              // 128 floats
#define SM_TOTAL 68608

__device__ __forceinline__ float silu_f(float v) {
    return __fdividef(v, 1.0f + __expf(-v));
}
__device__ __forceinline__ u32 smem_u32(const void* p) {
    u32 a; asm("{ .reg .u64 t; cvta.to.shared.u64 t, %1; cvt.u32.u64 %0, t; }"
               : "=r"(a) : "l"(p));
    return a;
}
// d[31:16] = bf16(hi_el), d[15:0] = bf16(lo_el)
__device__ __forceinline__ u32 bfpair(float hi_el, float lo_el) {
    u32 r; asm("cvt.rn.bf16x2.f32 %0, %1, %2;" : "=r"(r) : "f"(hi_el), "f"(lo_el));
    return r;
}
__device__ __forceinline__ void mma16816(float* d, u32 a0, u32 a1, u32 a2, u32 a3,
                                         u32 b0, u32 b1) {
    asm volatile("mma.sync.aligned.m16n8k16.row.col.f32.bf16.bf16.f32 "
        "{%0,%1,%2,%3}, {%4,%5,%6,%7}, {%8,%9}, {%0,%1,%2,%3};"
        : "+f"(d[0]), "+f"(d[1]), "+f"(d[2]), "+f"(d[3])
        : "r"(a0), "r"(a1), "r"(a2), "r"(a3), "r"(b0), "r"(b1));
}
__device__ __forceinline__ void cpa16(u32 dst, const void* src) {
    asm volatile("cp.async.cg.shared.global [%0], [%1], 16;"
                 :: "r"(dst), "l"(src) : "memory");
}
__device__ __forceinline__ void cpa_commit() {
    asm volatile("cp.async.commit_group;" ::: "memory");
}
__device__ __forceinline__ void cpa_wait0() {
    asm volatile("cp.async.wait_group 0;" ::: "memory");
}

__global__ void zero_all(int N) {
    size_t i = (size_t)blockIdx.x * blockDim.x + threadIdx.x;
    if (i < (size_t)N * DD) g_sums[i] = 0.f;
    if (i < (size_t)N) g_cnt[i] = 0.f;
    if (i < 128) { g_st1[i] = 0.f; g_st2[i] = 0.f; }
}

// MMA GEMM, 128-row tiles: C[M,64] = A'[M,64] @ Wsl[64,64] + add.
// A' = A (row-scaled by 1/max(cnt,1) if cnt). add = bias or addmat[idx?idx[n]:n];
// the addmat rows are prefetched into smem via cp.async, overlapped with MMA.
// stats (optional): per-column sum/sumsq of C.
// fp32 -> bf16 hi/lo split, 3-term mma.sync (hh + lh + hl), fp32 accum.
// Warp layout: warp w -> rows 64*(w>>2)..+63, cols 16*(w&3)..+15.
__global__ __launch_bounds__(256, 2) void gemm_mma(
    const float* __restrict__ A, const float* __restrict__ cnt,
    const float* __restrict__ Wsl, const float* __restrict__ bias,
    const float* __restrict__ addmat, const int* __restrict__ idx,
    float* __restrict__ C, float* __restrict__ stats, int M, int tiles)
{
    extern __shared__ char smem[];
    char*  sAhi = smem + SM_AHI;
    char*  sAlo = smem + SM_ALO;
    float* sGat = (float*)(smem + SM_GAT);
    int*   sIdx = (int*)(smem + SM_IDX);
    float* sst  = (float*)(smem + SM_SST);
    u32 gat_u = smem_u32(sGat);

    int tid  = threadIdx.x;
    int w    = tid >> 5, lane = tid & 31;
    int g    = lane >> 2, tq = lane & 3;
    int c0   = (w & 3) * 16;
    int mb   = (w >> 2) * 64;
    int sw   = g << 4;

    // W fragments in registers (hi + lo), two n8 col groups, whole kernel.
    u32 BH[2][4][2], BL[2][4][2];
    #pragma unroll
    for (int j = 0; j < 2; j++) {
        #pragma unroll
        for (int kt = 0; kt < 4; kt++) {
            #pragma unroll
            for (int b = 0; b < 2; b++) {
                int k = kt * 16 + tq * 2 + b * 8;
                int n = c0 + j * 8 + g;
                float w0 = Wsl[k * 64 + n], w1 = Wsl[(k + 1) * 64 + n];
                u32 h = bfpair(w1, w0);
                float w0h = __uint_as_float(h << 16);
                float w1h = __uint_as_float(h & 0xFFFF0000u);
                BH[j][kt][b] = h;
                BL[j][kt][b] = bfpair(w1 - w1h, w0 - w0h);
            }
        }
    }

    float ps[2][2] = {{0,0},{0,0}}, pq[2][2] = {{0,0},{0,0}};

    for (int tt = blockIdx.x; tt < tiles; tt += gridDim.x) {
        int base = tt * 128;
        __syncthreads();
        // stage idx for this tile
        if (idx && tid < 128) {
            int gn = base + tid;
            sIdx[tid] = (gn < M) ? idx[gn] : 0;
        }
        // convert A rows -> bf16 hi/lo planes (direct LDG)
        {
            const float4* src = (const float4*)A + (size_t)base * 16;
            #pragma unroll
            for (int i = tid; i < 2048; i += 256) {
                int r = i >> 4, c4 = i & 15;
                int gr = base + r;
                float4 v = make_float4(0.f, 0.f, 0.f, 0.f);
                if (gr < M) {
                    v = src[i];
                    if (cnt) {
                        float inv = __fdividef(1.0f, fmaxf(cnt[gr], 1.0f));
                        v.x *= inv; v.y *= inv; v.z *= inv; v.w *= inv;
                    }
                }
                u32 h01 = bfpair(v.y, v.x);
                u32 h23 = bfpair(v.w, v.z);
                float f0 = __uint_as_float(h01 << 16);
                float f1 = __uint_as_float(h01 & 0xFFFF0000u);
                float f2 = __uint_as_float(h23 << 16);
                float f3 = __uint_as_float(h23 & 0xFFFF0000u);
                u32 l01 = bfpair(v.y - f1, v.x - f0);
                u32 l23 = bfpair(v.w - f3, v.z - f2);
                int off = r * 128 + ((c4 * 8) ^ ((r & 7) << 4));
                *(uint2*)(sAhi + off) = make_uint2(h01, h23);
                *(uint2*)(sAlo + off) = make_uint2(l01, l23);
            }
        }
        __syncthreads();

        // prefetch gathered addmat rows -> sGat (overlapped with MMA)
        if (addmat) {
            #pragma unroll
            for (int i = tid; i < 2048; i += 256) {
                int r = i >> 4, q = i & 15;
                int gr = base + r;
                if (gr < M) {
                    int r2 = idx ? sIdx[r] : gr;
                    cpa16(gat_u + (u32)(r * 272 + q * 16),
                          addmat + (size_t)r2 * 64 + q * 4);
                }
            }
            cpa_commit();
        }

        float acc[4][2][4];
        #pragma unroll
        for (int mt = 0; mt < 4; mt++)
            #pragma unroll
            for (int j = 0; j < 2; j++)
                #pragma unroll
                for (int q = 0; q < 4; q++) acc[mt][j][q] = 0.f;

        #pragma unroll
        for (int kt = 0; kt < 4; kt++) {
            int k0 = ((kt * 32) ^ sw) + tq * 4;
            int k1 = ((kt * 32 + 16) ^ sw) + tq * 4;
            #pragma unroll
            for (int mt = 0; mt < 4; mt++) {
                int row = mb + mt * 16 + g;
                const char* ph = sAhi + row * 128;
                const char* pl = sAlo + row * 128;
                u32 a0 = *(const u32*)(ph + k0);
                u32 a1 = *(const u32*)(ph + 1024 + k0);   // row+8
                u32 a2 = *(const u32*)(ph + k1);
                u32 a3 = *(const u32*)(ph + 1024 + k1);
                u32 l0 = *(const u32*)(pl + k0);
                u32 l1 = *(const u32*)(pl + 1024 + k0);
                u32 l2 = *(const u32*)(pl + k1);
                u32 l3 = *(const u32*)(pl + 1024 + k1);
                #pragma unroll
                for (int j = 0; j < 2; j++) {
                    mma16816(acc[mt][j], a0, a1, a2, a3, BH[j][kt][0], BH[j][kt][1]);
                    mma16816(acc[mt][j], l0, l1, l2, l3, BH[j][kt][0], BH[j][kt][1]);
                    mma16816(acc[mt][j], a0, a1, a2, a3, BL[j][kt][0], BL[j][kt][1]);
                }
            }
        }
        if (addmat) { cpa_wait0(); }
        __syncthreads();   // gather buffer complete across all threads

        // Epilogue: + gather/bias (from smem), store, batch stats.
        #pragma unroll
        for (int mt = 0; mt < 4; mt++) {
            #pragma unroll
            for (int h = 0; h < 2; h++) {
                int rl = mb + mt * 16 + g + h * 8;
                int n = base + rl;
                if (n < M) {
                    #pragma unroll
                    for (int j = 0; j < 2; j++) {
                        int cj = c0 + j * 8 + 2 * tq;
                        float o0 = acc[mt][j][h * 2 + 0];
                        float o1 = acc[mt][j][h * 2 + 1];
                        float2 av = addmat
                            ? *(const float2*)&sGat[rl * 68 + cj]
                            : *(const float2*)(bias + cj);
                        o0 += av.x; o1 += av.y;
                        *(float2*)(C + (size_t)n * 64 + cj) = make_float2(o0, o1);
                        ps[j][0] += o0; pq[j][0] += o0 * o0;
                        ps[j][1] += o1; pq[j][1] += o1 * o1;
                    }
                }
            }
        }
    }

    if (!stats) return;
    __syncthreads();
    if (tid < 128) sst[tid] = 0.f;
    __syncthreads();
    #pragma unroll
    for (int j = 0; j < 2; j++) {
        int cj = c0 + j * 8 + 2 * tq;
        atomicAdd(&sst[cj], ps[j][0]);
        atomicAdd(&sst[cj + 1], ps[j][1]);
        atomicAdd(&sst[64 + cj], pq[j][0]);
        atomicAdd(&sst[64 + cj + 1], pq[j][1]);
    }
    __syncthreads();
    if (tid < 128) atomicAdd(&stats[tid], sst[tid]);
}

__global__ void finalize_kernel(const float* __restrict__ st,
                                const float* __restrict__ g,
                                const float* __restrict__ be,
                                float* __restrict__ ss, float invM)
{
    int j = threadIdx.x;
    if (j < 64) {
        float mu  = st[j] * invM;
        float var = fmaxf(st[64 + j] * invM - mu * mu, 0.f);
        float sc  = g[j] * rsqrtf(var + 1e-5f);
        ss[j]      = sc;
        ss[64 + j] = fmaf(-mu, sc, be[j]);
    }
}

__global__ __launch_bounds__(256) void scatter_kernel(
    const float4* __restrict__ H1, const int* __restrict__ colIdx,
    const float* __restrict__ ss, float4* __restrict__ sums,
    float* __restrict__ cnt, int E)
{
    __shared__ int scol[16];
    int ge0 = blockIdx.x * 16;
    int tid = threadIdx.x;
    if (tid < 16) { int ge = ge0 + tid; scol[tid] = (ge < E) ? colIdx[ge] : 0; }
    __syncthreads();
    int el = tid >> 4, q = tid & 15;
    int ge = ge0 + el;
    if (ge < E) {
        float4 h  = H1[(size_t)ge * 16 + q];
        float4 sc = *(const float4*)(ss + q * 4);
        float4 sh = *(const float4*)(ss + 64 + q * 4);
        float4 y;
        y.x = silu_f(fmaf(h.x, sc.x, sh.x));
        y.y = silu_f(fmaf(h.y, sc.y, sh.y));
        y.z = silu_f(fmaf(h.z, sc.z, sh.z));
        y.w = silu_f(fmaf(h.w, sc.w, sh.w));
        int c = scol[el];
        atomicAdd(&sums[(size_t)c * 16 + q], y);
        if (q == 0) atomicAdd(&cnt[c], 1.0f);
    }
}

__global__ void bn_silu_out(const float4* __restrict__ H2,
                            const float* __restrict__ ss,
                            float4* __restrict__ out, int n4)
{
    int i = blockIdx.x * blockDim.x + threadIdx.x;
    if (i < n4) {
        int q = i & 15;
        float4 h  = H2[i];
        float4 sc = *(const float4*)(ss + q * 4);
        float4 sh = *(const float4*)(ss + 64 + q * 4);
        float4 y;
        y.x = silu_f(fmaf(h.x, sc.x, sh.x));
        y.y = silu_f(fmaf(h.y, sc.y, sh.y));
        y.z = silu_f(fmaf(h.z, sc.z, sh.z));
        y.w = silu_f(fmaf(h.w, sc.w, sh.w));
        out[i] = y;
    }
}

extern "C" void kernel_launch(void* const* d_in, const int* in_sizes, int n_in,
                              void* d_out, int out_size)
{
    if (n_in < 12) return;
    const float* x   = (const float*)d_in[0];
    const float* ea  = (const float*)d_in[1];
    const float* W1  = (const float*)d_in[3];
    const float* b1  = (const float*)d_in[4];
    const float* g1  = (const float*)d_in[5];
    const float* be1 = (const float*)d_in[6];
    const float* W2  = (const float*)d_in[7];
    const float* b2  = (const float*)d_in[8];
    const float* g2  = (const float*)d_in[9];
    const float* be2 = (const float*)d_in[10];
    const int*   ei  = (const int*)d_in[11];   // int32 (jax x64 disabled)

    int N = in_sizes[0] / DD;
    int E = in_sizes[1] / DD;
    if (N <= 0 || E <= 0 || N > MAXN || E > MAXE) return;

    void *p0, *p1, *p2, *p3, *p4, *p5, *p6, *p7, *p8, *p9;
    cudaGetSymbolAddress(&p0, g_xa);   cudaGetSymbolAddress(&p1, g_xb);
    cudaGetSymbolAddress(&p2, g_h1);   cudaGetSymbolAddress(&p3, g_h2);
    cudaGetSymbolAddress(&p4, g_sums); cudaGetSymbolAddress(&p5, g_cnt);
    cudaGetSymbolAddress(&p6, g_st1);  cudaGetSymbolAddress(&p7, g_st2);
    cudaGetSymbolAddress(&p8, g_ss1);  cudaGetSymbolAddress(&p9, g_ss2);
    float *xa = (float*)p0, *xb = (float*)p1, *h1 = (float*)p2, *h2 = (float*)p3;
    float *sums = (float*)p4, *cnt = (float*)p5;
    float *st1 = (float*)p6, *st2 = (float*)p7, *ss1 = (float*)p8, *ss2 = (float*)p9;

    cudaFuncSetAttribute(gemm_mma, cudaFuncAttributeMaxDynamicSharedMemorySize, SM_TOTAL);

    int tN = (N + 127) / 128;
    int tE = (E + 127) / 128;
    int zb = (int)(((size_t)N * DD + 255) / 256);
    const int G = 592;

    zero_all<<<zb, 256>>>(N);
    gemm_mma<<<G, 256, SM_TOTAL>>>(x, nullptr, W1, b1, nullptr, nullptr, xa, nullptr, N, tN);
    gemm_mma<<<G, 256, SM_TOTAL>>>(x, nullptr, W2, b2, nullptr, nullptr, xb, nullptr, N, tN);
    gemm_mma<<<G, 256, SM_TOTAL>>>(ea, nullptr, W1 + 4096, nullptr, xa, ei, h1, st1, E, tE);
    finalize_kernel<<<1, 64>>>(st1, g1, be1, ss1, 1.0f / (float)E);
    scatter_kernel<<<(E + 15) / 16, 256>>>((const float4*)h1, ei + E, ss1,
                                           (float4*)sums, cnt, E);
    gemm_mma<<<G, 256, SM_TOTAL>>>(sums, cnt, W2 + 4096, nullptr, xb, nullptr, h2, st2, N, tN);
    finalize_kernel<<<1, 64>>>(st2, g2, be2, ss2, 1.0f / (float)N);
    bn_silu_out<<<(N * 16 + 255) / 256, 256>>>((const float4*)h2, ss2,
                                               (float4*)d_out, N * 16);
}

// round 15
// speedup vs baseline: 1.3667x; 1.3667x over previous
#include <cuda_runtime.h>

#define DD 64
#define MAXN 100000
#define MAXE 1000000
typedef unsigned long long u64;
typedef unsigned int u32;

__device__ float g_xa[(size_t)MAXN * DD];
__device__ float g_xb[(size_t)MAXN * DD];
__device__ float g_h1[(size_t)MAXE * DD];
__device__ float g_h2[(size_t)MAXN * DD];
__device__ float g_sums[(size_t)MAXN * DD];
__device__ float g_cnt[MAXN];
__device__ float g_st1[128], g_st2[128], g_ss1[128], g_ss2[128];

__device__ __forceinline__ float silu_f(float v) {
    return __fdividef(v, 1.0f + __expf(-v));
}
// d[31:16] = bf16(hi_el), d[15:0] = bf16(lo_el)
__device__ __forceinline__ u32 bfpair(float hi_el, float lo_el) {
    u32 r; asm("cvt.rn.bf16x2.f32 %0, %1, %2;" : "=r"(r) : "f"(hi_el), "f"(lo_el));
    return r;
}
__device__ __forceinline__ void mma16816(float* d, u32 a0, u32 a1, u32 a2, u32 a3,
                                         u32 b0, u32 b1) {
    asm volatile("mma.sync.aligned.m16n8k16.row.col.f32.bf16.bf16.f32 "
        "{%0,%1,%2,%3}, {%4,%5,%6,%7}, {%8,%9}, {%0,%1,%2,%3};"
        : "+f"(d[0]), "+f"(d[1]), "+f"(d[2]), "+f"(d[3])
        : "r"(a0), "r"(a1), "r"(a2), "r"(a3), "r"(b0), "r"(b1));
}

__global__ void zero_all(int N) {
    size_t i = (size_t)blockIdx.x * blockDim.x + threadIdx.x;
    if (i < (size_t)N * DD) g_sums[i] = 0.f;
    if (i < (size_t)N) g_cnt[i] = 0.f;
    if (i < 128) { g_st1[i] = 0.f; g_st2[i] = 0.f; }
}

// MMA GEMM, 128-row tiles: C[M,64] = A'[M,64] @ Wsl[64,64] + add.
// A' = A (row-scaled by 1/max(cnt,1) if cnt). add = bias or addmat[idx?idx[n]:n].
// stats (optional): per-column sum/sumsq of C.
// fp32 -> bf16 hi/lo split, 3-term mma.sync (hh + lh + hl), fp32 accum.
// Warp layout (4 row-groups x 2 col-groups to halve A-frag LDS redundancy):
//   warp w -> rows 32*(w&3)..+31, cols 32*(w>>2)..+31.
__global__ __launch_bounds__(256, 2) void gemm_mma(
    const float* __restrict__ A, const float* __restrict__ cnt,
    const float* __restrict__ Wsl, const float* __restrict__ bias,
    const float* __restrict__ addmat, const int* __restrict__ idx,
    float* __restrict__ C, float* __restrict__ stats, int M, int tiles)
{
    __shared__ char sAhi[128 * 128];   // 16 KB: [row][k] bf16, swizzled
    __shared__ char sAlo[128 * 128];   // 16 KB
    __shared__ float sst[128];

    int tid  = threadIdx.x;
    int w    = tid >> 5, lane = tid & 31;
    int g    = lane >> 2, tq = lane & 3;
    int mb   = (w & 3) * 32;
    int c0   = (w >> 2) * 32;
    int sw   = g << 4;

    // W fragments in registers (hi + lo), four n8 col groups, whole kernel.
    u32 BH[4][4][2], BL[4][4][2];
    #pragma unroll
    for (int j = 0; j < 4; j++) {
        #pragma unroll
        for (int kt = 0; kt < 4; kt++) {
            #pragma unroll
            for (int b = 0; b < 2; b++) {
                int k = kt * 16 + tq * 2 + b * 8;
                int n = c0 + j * 8 + g;
                float w0 = Wsl[k * 64 + n], w1 = Wsl[(k + 1) * 64 + n];
                u32 h = bfpair(w1, w0);
                float w0h = __uint_as_float(h << 16);
                float w1h = __uint_as_float(h & 0xFFFF0000u);
                BH[j][kt][b] = h;
                BL[j][kt][b] = bfpair(w1 - w1h, w0 - w0h);
            }
        }
    }

    float ps[4][2] = {{0,0},{0,0},{0,0},{0,0}};
    float pq[4][2] = {{0,0},{0,0},{0,0},{0,0}};

    for (int tt = blockIdx.x; tt < tiles; tt += gridDim.x) {
        int base = tt * 128;
        __syncthreads();
        // Fill: convert A rows to bf16 hi/lo planes (swizzled).
        {
            const float4* src = (const float4*)A + (size_t)base * 16;
            #pragma unroll
            for (int i = tid; i < 2048; i += 256) {
                int r = i >> 4, c4 = i & 15;
                int gr = base + r;
                float4 v = make_float4(0.f, 0.f, 0.f, 0.f);
                if (gr < M) {
                    v = src[i];
                    if (cnt) {
                        float inv = __fdividef(1.0f, fmaxf(cnt[gr], 1.0f));
                        v.x *= inv; v.y *= inv; v.z *= inv; v.w *= inv;
                    }
                }
                u32 h01 = bfpair(v.y, v.x);
                u32 h23 = bfpair(v.w, v.z);
                float f0 = __uint_as_float(h01 << 16);
                float f1 = __uint_as_float(h01 & 0xFFFF0000u);
                float f2 = __uint_as_float(h23 << 16);
                float f3 = __uint_as_float(h23 & 0xFFFF0000u);
                u32 l01 = bfpair(v.y - f1, v.x - f0);
                u32 l23 = bfpair(v.w - f3, v.z - f2);
                int off = r * 128 + ((c4 * 8) ^ ((r & 7) << 4));
                *(uint2*)(sAhi + off) = make_uint2(h01, h23);
                *(uint2*)(sAlo + off) = make_uint2(l01, l23);
            }
        }
        __syncthreads();

        float acc[2][4][4];
        #pragma unroll
        for (int mt = 0; mt < 2; mt++)
            #pragma unroll
            for (int j = 0; j < 4; j++)
                #pragma unroll
                for (int q = 0; q < 4; q++) acc[mt][j][q] = 0.f;

        #pragma unroll
        for (int kt = 0; kt < 4; kt++) {
            int k0 = ((kt * 32) ^ sw) + tq * 4;
            int k1 = ((kt * 32 + 16) ^ sw) + tq * 4;
            #pragma unroll
            for (int mt = 0; mt < 2; mt++) {
                int row = mb + mt * 16 + g;
                const char* ph = sAhi + row * 128;
                const char* pl = sAlo + row * 128;
                u32 a0 = *(const u32*)(ph + k0);
                u32 a1 = *(const u32*)(ph + 1024 + k0);   // row+8
                u32 a2 = *(const u32*)(ph + k1);
                u32 a3 = *(const u32*)(ph + 1024 + k1);
                u32 l0 = *(const u32*)(pl + k0);
                u32 l1 = *(const u32*)(pl + 1024 + k0);
                u32 l2 = *(const u32*)(pl + k1);
                u32 l3 = *(const u32*)(pl + 1024 + k1);
                #pragma unroll
                for (int j = 0; j < 4; j++) {
                    mma16816(acc[mt][j], a0, a1, a2, a3, BH[j][kt][0], BH[j][kt][1]);
                    mma16816(acc[mt][j], l0, l1, l2, l3, BH[j][kt][0], BH[j][kt][1]);
                    mma16816(acc[mt][j], a0, a1, a2, a3, BL[j][kt][0], BL[j][kt][1]);
                }
            }
        }
        // Epilogue: + gather/bias, store, batch stats.
        #pragma unroll
        for (int mt = 0; mt < 2; mt++) {
            #pragma unroll
            for (int h = 0; h < 2; h++) {
                int n = base + mb + mt * 16 + g + h * 8;
                if (n < M) {
                    int r2 = n;
                    if (addmat && idx) r2 = idx[n];
                    #pragma unroll
                    for (int j = 0; j < 4; j++) {
                        int cj = c0 + j * 8 + 2 * tq;
                        float o0 = acc[mt][j][h * 2 + 0];
                        float o1 = acc[mt][j][h * 2 + 1];
                        float2 av = addmat
                            ? *(const float2*)(addmat + (size_t)r2 * 64 + cj)
                            : *(const float2*)(bias + cj);
                        o0 += av.x; o1 += av.y;
                        *(float2*)(C + (size_t)n * 64 + cj) = make_float2(o0, o1);
                        ps[j][0] += o0; pq[j][0] += o0 * o0;
                        ps[j][1] += o1; pq[j][1] += o1 * o1;
                    }
                }
            }
        }
    }

    if (!stats) return;
    __syncthreads();
    if (tid < 128) sst[tid] = 0.f;
    __syncthreads();
    #pragma unroll
    for (int j = 0; j < 4; j++) {
        int cj = c0 + j * 8 + 2 * tq;
        atomicAdd(&sst[cj], ps[j][0]);
        atomicAdd(&sst[cj + 1], ps[j][1]);
        atomicAdd(&sst[64 + cj], pq[j][0]);
        atomicAdd(&sst[64 + cj + 1], pq[j][1]);
    }
    __syncthreads();
    if (tid < 128) atomicAdd(&stats[tid], sst[tid]);
}

__global__ void finalize_kernel(const float* __restrict__ st,
                                const float* __restrict__ g,
                                const float* __restrict__ be,
                                float* __restrict__ ss, float invM)
{
    int j = threadIdx.x;
    if (j < 64) {
        float mu  = st[j] * invM;
        float var = fmaxf(st[64 + j] * invM - mu * mu, 0.f);
        float sc  = g[j] * rsqrtf(var + 1e-5f);
        ss[j]      = sc;
        ss[64 + j] = fmaf(-mu, sc, be[j]);
    }
}

__global__ __launch_bounds__(256) void scatter_kernel(
    const float4* __restrict__ H1, const int* __restrict__ colIdx,
    const float* __restrict__ ss, float4* __restrict__ sums,
    float* __restrict__ cnt, int E)
{
    __shared__ int scol[16];
    int ge0 = blockIdx.x * 16;
    int tid = threadIdx.x;
    if (tid < 16) { int ge = ge0 + tid; scol[tid] = (ge < E) ? colIdx[ge] : 0; }
    __syncthreads();
    int el = tid >> 4, q = tid & 15;
    int ge = ge0 + el;
    if (ge < E) {
        float4 h  = H1[(size_t)ge * 16 + q];
        float4 sc = *(const float4*)(ss + q * 4);
        float4 sh = *(const float4*)(ss + 64 + q * 4);
        float4 y;
        y.x = silu_f(fmaf(h.x, sc.x, sh.x));
        y.y = silu_f(fmaf(h.y, sc.y, sh.y));
        y.z = silu_f(fmaf(h.z, sc.z, sh.z));
        y.w = silu_f(fmaf(h.w, sc.w, sh.w));
        int c = scol[el];
        atomicAdd(&sums[(size_t)c * 16 + q], y);
        if (q == 0) atomicAdd(&cnt[c], 1.0f);
    }
}

__global__ void bn_silu_out(const float4* __restrict__ H2,
                            const float* __restrict__ ss,
                            float4* __restrict__ out, int n4)
{
    int i = blockIdx.x * blockDim.x + threadIdx.x;
    if (i < n4) {
        int q = i & 15;
        float4 h  = H2[i];
        float4 sc = *(const float4*)(ss + q * 4);
        float4 sh = *(const float4*)(ss + 64 + q * 4);
        float4 y;
        y.x = silu_f(fmaf(h.x, sc.x, sh.x));
        y.y = silu_f(fmaf(h.y, sc.y, sh.y));
        y.z = silu_f(fmaf(h.z, sc.z, sh.z));
        y.w = silu_f(fmaf(h.w, sc.w, sh.w));
        out[i] = y;
    }
}

extern "C" void kernel_launch(void* const* d_in, const int* in_sizes, int n_in,
                              void* d_out, int out_size)
{
    if (n_in < 12) return;
    const float* x   = (const float*)d_in[0];
    const float* ea  = (const float*)d_in[1];
    const float* W1  = (const float*)d_in[3];
    const float* b1  = (const float*)d_in[4];
    const float* g1  = (const float*)d_in[5];
    const float* be1 = (const float*)d_in[6];
    const float* W2  = (const float*)d_in[7];
    const float* b2  = (const float*)d_in[8];
    const float* g2  = (const float*)d_in[9];
    const float* be2 = (const float*)d_in[10];
    const int*   ei  = (const int*)d_in[11];   // int32 (jax x64 disabled)

    int N = in_sizes[0] / DD;
    int E = in_sizes[1] / DD;
    if (N <= 0 || E <= 0 || N > MAXN || E > MAXE) return;

    void *p0, *p1, *p2, *p3, *p4, *p5, *p6, *p7, *p8, *p9;
    cudaGetSymbolAddress(&p0, g_xa);   cudaGetSymbolAddress(&p1, g_xb);
    cudaGetSymbolAddress(&p2, g_h1);   cudaGetSymbolAddress(&p3, g_h2);
    cudaGetSymbolAddress(&p4, g_sums); cudaGetSymbolAddress(&p5, g_cnt);
    cudaGetSymbolAddress(&p6, g_st1);  cudaGetSymbolAddress(&p7, g_st2);
    cudaGetSymbolAddress(&p8, g_ss1);  cudaGetSymbolAddress(&p9, g_ss2);
    float *xa = (float*)p0, *xb = (float*)p1, *h1 = (float*)p2, *h2 = (float*)p3;
    float *sums = (float*)p4, *cnt = (float*)p5;
    float *st1 = (float*)p6, *st2 = (float*)p7, *ss1 = (float*)p8, *ss2 = (float*)p9;

    int tN = (N + 127) / 128;
    int tE = (E + 127) / 128;
    int zb = (int)(((size_t)N * DD + 255) / 256);
    const int G = 592;

    zero_all<<<zb, 256>>>(N);
    gemm_mma<<<G, 256>>>(x, nullptr, W1, b1, nullptr, nullptr, xa, nullptr, N, tN);
    gemm_mma<<<G, 256>>>(x, nullptr, W2, b2, nullptr, nullptr, xb, nullptr, N, tN);
    gemm_mma<<<G, 256>>>(ea, nullptr, W1 + 4096, nullptr, xa, ei, h1, st1, E, tE);
    finalize_kernel<<<1, 64>>>(st1, g1, be1, ss1, 1.0f / (float)E);
    scatter_kernel<<<(E + 15) / 16, 256>>>((const float4*)h1, ei + E, ss1,
                                           (float4*)sums, cnt, E);
    gemm_mma<<<G, 256>>>(sums, cnt, W2 + 4096, nullptr, xb, nullptr, h2, st2, N, tN);
    finalize_kernel<<<1, 64>>>(st2, g2, be2, ss2, 1.0f / (float)N);
    bn_silu_out<<<(N * 16 + 255) / 256, 256>>>((const float4*)h2, ss2,
                                               (float4*)d_out, N * 16);
}

// round 17
// speedup vs baseline: 1.4973x; 1.0955x over previous
#include <cuda_runtime.h>

#define DD 64
#define MAXN 100000
#define MAXE 1000000
typedef unsigned long long u64;
typedef unsigned int u32;

__device__ float g_xa[(size_t)MAXN * DD];
__device__ float g_xb[(size_t)MAXN * DD];
__device__ float g_h1[(size_t)MAXE * DD];
__device__ float g_h2[(size_t)MAXN * DD];
__device__ float g_sums[(size_t)MAXN * DD];
__device__ float g_cnt[MAXN];
__device__ float g_st1[128], g_st2[128], g_ss1[128], g_ss2[128];

__device__ __forceinline__ float silu_f(float v) {
    return __fdividef(v, 1.0f + __expf(-v));
}
// d[31:16] = bf16(hi_el), d[15:0] = bf16(lo_el)
__device__ __forceinline__ u32 bfpair(float hi_el, float lo_el) {
    u32 r; asm("cvt.rn.bf16x2.f32 %0, %1, %2;" : "=r"(r) : "f"(hi_el), "f"(lo_el));
    return r;
}
__device__ __forceinline__ void mma16816(float* d, u32 a0, u32 a1, u32 a2, u32 a3,
                                         u32 b0, u32 b1) {
    asm volatile("mma.sync.aligned.m16n8k16.row.col.f32.bf16.bf16.f32 "
        "{%0,%1,%2,%3}, {%4,%5,%6,%7}, {%8,%9}, {%0,%1,%2,%3};"
        : "+f"(d[0]), "+f"(d[1]), "+f"(d[2]), "+f"(d[3])
        : "r"(a0), "r"(a1), "r"(a2), "r"(a3), "r"(b0), "r"(b1));
}

__global__ void zero_all(int N) {
    size_t i = (size_t)blockIdx.x * blockDim.x + threadIdx.x;
    if (i < (size_t)N * DD) g_sums[i] = 0.f;
    if (i < (size_t)N) g_cnt[i] = 0.f;
    if (i < 128) { g_st1[i] = 0.f; g_st2[i] = 0.f; }
}

// MMA GEMM, 128-row tiles: C[M,64] = inv(n)*(A[M,64] @ Wsl[64,64]) + add,
// inv(n) = 1/max(cnt[n],1) if cnt else 1. add = bias or addmat[idx?idx[n]:n].
// stats (optional): per-column sum/sumsq of C.
// fp32 -> bf16 hi/lo split, 3-term mma.sync (hh + lh + hl), fp32 accum.
// Warp layout: warp w -> rows 32*(w&3)..+31, cols 32*(w>>2)..+31.
__global__ __launch_bounds__(256, 2) void gemm_mma(
    const float* __restrict__ A, const float* __restrict__ cnt,
    const float* __restrict__ Wsl, const float* __restrict__ bias,
    const float* __restrict__ addmat, const int* __restrict__ idx,
    float* __restrict__ C, float* __restrict__ stats, int M, int tiles)
{
    __shared__ char sAhi[128 * 128];   // 16 KB: [row][k] bf16, swizzled
    __shared__ char sAlo[128 * 128];   // 16 KB
    __shared__ float sst[128];

    int tid  = threadIdx.x;
    int w    = tid >> 5, lane = tid & 31;
    int g    = lane >> 2, tq = lane & 3;
    int mb   = (w & 3) * 32;
    int c0   = (w >> 2) * 32;
    int sw   = g << 4;

    // W fragments in registers (hi + lo), four n8 col groups, whole kernel.
    u32 BH[4][4][2], BL[4][4][2];
    #pragma unroll
    for (int j = 0; j < 4; j++) {
        #pragma unroll
        for (int kt = 0; kt < 4; kt++) {
            #pragma unroll
            for (int b = 0; b < 2; b++) {
                int k = kt * 16 + tq * 2 + b * 8;
                int n = c0 + j * 8 + g;
                float w0 = Wsl[k * 64 + n], w1 = Wsl[(k + 1) * 64 + n];
                u32 h = bfpair(w1, w0);
                float w0h = __uint_as_float(h << 16);
                float w1h = __uint_as_float(h & 0xFFFF0000u);
                BH[j][kt][b] = h;
                BL[j][kt][b] = bfpair(w1 - w1h, w0 - w0h);
            }
        }
    }

    float ps[4][2] = {{0,0},{0,0},{0,0},{0,0}};
    float pq[4][2] = {{0,0},{0,0},{0,0},{0,0}};

    for (int tt = blockIdx.x; tt < tiles; tt += gridDim.x) {
        int base = tt * 128;
        __syncthreads();
        // Fill: convert A rows to bf16 hi/lo planes (swizzled).
        {
            const float4* src = (const float4*)A + (size_t)base * 16;
            #pragma unroll
            for (int i = tid; i < 2048; i += 256) {
                int r = i >> 4, c4 = i & 15;
                int gr = base + r;
                float4 v = make_float4(0.f, 0.f, 0.f, 0.f);
                if (gr < M) v = src[i];
                u32 h01 = bfpair(v.y, v.x);
                u32 h23 = bfpair(v.w, v.z);
                float f0 = __uint_as_float(h01 << 16);
                float f1 = __uint_as_float(h01 & 0xFFFF0000u);
                float f2 = __uint_as_float(h23 << 16);
                float f3 = __uint_as_float(h23 & 0xFFFF0000u);
                u32 l01 = bfpair(v.y - f1, v.x - f0);
                u32 l23 = bfpair(v.w - f3, v.z - f2);
                int off = r * 128 + ((c4 * 8) ^ ((r & 7) << 4));
                *(uint2*)(sAhi + off) = make_uint2(h01, h23);
                *(uint2*)(sAlo + off) = make_uint2(l01, l23);
            }
        }
        __syncthreads();

        float acc[2][4][4];
        #pragma unroll
        for (int mt = 0; mt < 2; mt++)
            #pragma unroll
            for (int j = 0; j < 4; j++)
                #pragma unroll
                for (int q = 0; q < 4; q++) acc[mt][j][q] = 0.f;

        #pragma unroll
        for (int kt = 0; kt < 4; kt++) {
            int k0 = ((kt * 32) ^ sw) + tq * 4;
            int k1 = ((kt * 32 + 16) ^ sw) + tq * 4;
            #pragma unroll
            for (int mt = 0; mt < 2; mt++) {
                int row = mb + mt * 16 + g;
                const char* ph = sAhi + row * 128;
                const char* pl = sAlo + row * 128;
                u32 a0 = *(const u32*)(ph + k0);
                u32 a1 = *(const u32*)(ph + 1024 + k0);   // row+8
                u32 a2 = *(const u32*)(ph + k1);
                u32 a3 = *(const u32*)(ph + 1024 + k1);
                u32 l0 = *(const u32*)(pl + k0);
                u32 l1 = *(const u32*)(pl + 1024 + k0);
                u32 l2 = *(const u32*)(pl + k1);
                u32 l3 = *(const u32*)(pl + 1024 + k1);
                #pragma unroll
                for (int j = 0; j < 4; j++) {
                    mma16816(acc[mt][j], a0, a1, a2, a3, BH[j][kt][0], BH[j][kt][1]);
                    mma16816(acc[mt][j], l0, l1, l2, l3, BH[j][kt][0], BH[j][kt][1]);
                    mma16816(acc[mt][j], a0, a1, a2, a3, BL[j][kt][0], BL[j][kt][1]);
                }
            }
        }
        // Epilogue: row scale (cnt), + gather/bias, store, batch stats.
        #pragma unroll
        for (int mt = 0; mt < 2; mt++) {
            #pragma unroll
            for (int h = 0; h < 2; h++) {
                int n = base + mb + mt * 16 + g + h * 8;
                if (n < M) {
                    float m = 1.0f;
                    if (cnt) m = __fdividef(1.0f, fmaxf(cnt[n], 1.0f));
                    int r2 = n;
                    if (addmat && idx) r2 = idx[n];
                    #pragma unroll
                    for (int j = 0; j < 4; j++) {
                        int cj = c0 + j * 8 + 2 * tq;
                        float2 av = addmat
                            ? *(const float2*)(addmat + (size_t)r2 * 64 + cj)
                            : *(const float2*)(bias + cj);
                        float o0 = fmaf(acc[mt][j][h * 2 + 0], m, av.x);
                        float o1 = fmaf(acc[mt][j][h * 2 + 1], m, av.y);
                        *(float2*)(C + (size_t)n * 64 + cj) = make_float2(o0, o1);
                        ps[j][0] += o0; pq[j][0] += o0 * o0;
                        ps[j][1] += o1; pq[j][1] += o1 * o1;
                    }
                }
            }
        }
    }

    if (!stats) return;
    __syncthreads();
    if (tid < 128) sst[tid] = 0.f;
    __syncthreads();
    #pragma unroll
    for (int j = 0; j < 4; j++) {
        int cj = c0 + j * 8 + 2 * tq;
        atomicAdd(&sst[cj], ps[j][0]);
        atomicAdd(&sst[cj + 1], ps[j][1]);
        atomicAdd(&sst[64 + cj], pq[j][0]);
        atomicAdd(&sst[64 + cj + 1], pq[j][1]);
    }
    __syncthreads();
    if (tid < 128) atomicAdd(&stats[tid], sst[tid]);
}

__global__ void finalize_kernel(const float* __restrict__ st,
                                const float* __restrict__ g,
                                const float* __restrict__ be,
                                float* __restrict__ ss, float invM)
{
    int j = threadIdx.x;
    if (j < 64) {
        float mu  = st[j] * invM;
        float var = fmaxf(st[64 + j] * invM - mu * mu, 0.f);
        float sc  = g[j] * rsqrtf(var + 1e-5f);
        ss[j]      = sc;
        ss[64 + j] = fmaf(-mu, sc, be[j]);
    }
}

// BN1+SiLU on h1, scatter-add. 64 edges/block, 4 per thread for MLP=4.
__global__ __launch_bounds__(256) void scatter_kernel(
    const float4* __restrict__ H1, const int* __restrict__ colIdx,
    const float* __restrict__ ss, float4* __restrict__ sums,
    float* __restrict__ cnt, int E)
{
    __shared__ int scol[64];
    int tid = threadIdx.x;
    int q = tid & 15, eg = tid >> 4;
    int base = blockIdx.x * 64;
    if (tid < 64) {
        int ge = base + tid;
        scol[tid] = (ge < E) ? colIdx[ge] : 0;
    }
    __syncthreads();
    float4 sc = *(const float4*)(ss + q * 4);
    float4 sh = *(const float4*)(ss + 64 + q * 4);

    float4 h[4];
    #pragma unroll
    for (int u = 0; u < 4; u++) {
        int ge = base + eg + u * 16;
        if (ge < E) h[u] = H1[(size_t)ge * 16 + q];
    }
    #pragma unroll
    for (int u = 0; u < 4; u++) {
        int ge = base + eg + u * 16;
        if (ge < E) {
            float4 y;
            y.x = silu_f(fmaf(h[u].x, sc.x, sh.x));
            y.y = silu_f(fmaf(h[u].y, sc.y, sh.y));
            y.z = silu_f(fmaf(h[u].z, sc.z, sh.z));
            y.w = silu_f(fmaf(h[u].w, sc.w, sh.w));
            int c = scol[eg + u * 16];
            atomicAdd(&sums[(size_t)c * 16 + q], y);
            if (q == 0) atomicAdd(&cnt[c], 1.0f);
        }
    }
}

__global__ void bn_silu_out(const float4* __restrict__ H2,
                            const float* __restrict__ ss,
                            float4* __restrict__ out, int n4)
{
    int i = blockIdx.x * blockDim.x + threadIdx.x;
    if (i < n4) {
        int q = i & 15;
        float4 h  = H2[i];
        float4 sc = *(const float4*)(ss + q * 4);
        float4 sh = *(const float4*)(ss + 64 + q * 4);
        float4 y;
        y.x = silu_f(fmaf(h.x, sc.x, sh.x));
        y.y = silu_f(fmaf(h.y, sc.y, sh.y));
        y.z = silu_f(fmaf(h.z, sc.z, sh.z));
        y.w = silu_f(fmaf(h.w, sc.w, sh.w));
        out[i] = y;
    }
}

extern "C" void kernel_launch(void* const* d_in, const int* in_sizes, int n_in,
                              void* d_out, int out_size)
{
    if (n_in < 12) return;
    const float* x   = (const float*)d_in[0];
    const float* ea  = (const float*)d_in[1];
    const float* W1  = (const float*)d_in[3];
    const float* b1  = (const float*)d_in[4];
    const float* g1  = (const float*)d_in[5];
    const float* be1 = (const float*)d_in[6];
    const float* W2  = (const float*)d_in[7];
    const float* b2  = (const float*)d_in[8];
    const float* g2  = (const float*)d_in[9];
    const float* be2 = (const float*)d_in[10];
    const int*   ei  = (const int*)d_in[11];   // int32 (jax x64 disabled)

    int N = in_sizes[0] / DD;
    int E = in_sizes[1] / DD;
    if (N <= 0 || E <= 0 || N > MAXN || E > MAXE) return;

    void *p0, *p1, *p2, *p3, *p4, *p5, *p6, *p7, *p8, *p9;
    cudaGetSymbolAddress(&p0, g_xa);   cudaGetSymbolAddress(&p1, g_xb);
    cudaGetSymbolAddress(&p2, g_h1);   cudaGetSymbolAddress(&p3, g_h2);
    cudaGetSymbolAddress(&p4, g_sums); cudaGetSymbolAddress(&p5, g_cnt);
    cudaGetSymbolAddress(&p6, g_st1);  cudaGetSymbolAddress(&p7, g_st2);
    cudaGetSymbolAddress(&p8, g_ss1);  cudaGetSymbolAddress(&p9, g_ss2);
    float *xa = (float*)p0, *xb = (float*)p1, *h1 = (float*)p2, *h2 = (float*)p3;
    float *sums = (float*)p4, *cnt = (float*)p5;
    float *st1 = (float*)p6, *st2 = (float*)p7, *ss1 = (float*)p8, *ss2 = (float*)p9;

    int tN = (N + 127) / 128;
    int tE = (E + 127) / 128;
    int zb = (int)(((size_t)N * DD + 255) / 256);
    const int G = 592;

    zero_all<<<zb, 256>>>(N);
    gemm_mma<<<G, 256>>>(x, nullptr, W1, b1, nullptr, nullptr, xa, nullptr, N, tN);
    gemm_mma<<<G, 256>>>(x, nullptr, W2, b2, nullptr, nullptr, xb, nullptr, N, tN);
    gemm_mma<<<G, 256>>>(ea, nullptr, W1 + 4096, nullptr, xa, ei, h1, st1, E, tE);
    finalize_kernel<<<1, 64>>>(st1, g1, be1, ss1, 1.0f / (float)E);
    scatter_kernel<<<(E + 63) / 64, 256>>>((const float4*)h1, ei + E, ss1,
                                           (float4*)sums, cnt, E);
    gemm_mma<<<G, 256>>>(sums, cnt, W2 + 4096, nullptr, xb, nullptr, h2, st2, N, tN);
    finalize_kernel<<<1, 64>>>(st2, g2, be2, ss2, 1.0f / (float)N);
    bn_silu_out<<<(N * 16 + 255) / 256, 256>>>((const float4*)h2, ss2,
                                               (float4*)d_out, N * 16);
}